// round 14
// baseline (speedup 1.0000x reference)
#include <cuda_runtime.h>

// Model_21569325760600: structure-module forward.
// SINGLE-stream occupancy experiment: R7's refinements (static chain tables,
// identity-parent jump rounds, leader-direct loads, staged R flush) with one
// 4-residue stream per warp-iter at __launch_bounds__(192,7) -> 48-reg budget,
// 42 warps/SM. Theory: L1 utilization tracks occupancy.

#define NRES  22
#define NE    66
#define FULLM 0xffffffffu

__device__ __align__(16) float d_t2[NE * 96];
__device__ __align__(16) float d_r2[NE * 96];
__device__ int d_chain[NRES * 8];

__global__ void reformat_kernel(const float* __restrict__ g_trans,   // [66,8,12]
                                const float* __restrict__ g_rigid,   // [66,24,3]
                                const int*   __restrict__ g_tdep) {  // [22,8]
    __shared__ int sp[NRES][8];
    int t = threadIdx.x;
    if (blockIdx.x < NE) {
        if (t < 96) {
            int e = blockIdx.x;
            int j4 = t >> 5;
            int li = (t >> 2) & 7;
            int k  = t & 3;
            d_t2[e * 96 + t] = g_trans[e * 96 + li * 12 + j4 * 4 + k];
            d_r2[e * 96 + t] = (k < 3) ? g_rigid[e * 72 + (li * 3 + j4) * 3 + k] : 0.0f;
        }
        return;
    }
    if (t < NRES * 8) {
        int rt = t >> 3, li = t & 7;
        int dd = g_tdep[rt * 8 + li];
        int imm = (li != 0 && dd >= li) ? 1 : 0;
        int p0 = (li != 0 && dd < li) ? dd : -1;
        sp[rt][li] = p0;
        __syncthreads();
        int p1 = (p0 >= 0) ? sp[rt][p0] : -1;
        __syncthreads();
        sp[rt][li] = p1;
        __syncthreads();
        int p2 = (p1 >= 0) ? sp[rt][p1] : -1;
        d_chain[t] = (dd & 0x7F) | (imm << 7) |
                     ((p0 & 0xFF) << 8) | ((p1 & 0xFF) << 16) | ((p2 & 0xFF) << 24);
    }
}

__device__ __forceinline__ void combine_tf(const float* __restrict__ X,
                                           const float* __restrict__ Y,
                                           float* __restrict__ C) {
#pragma unroll
    for (int i = 0; i < 3; i++) {
#pragma unroll
        for (int j = 0; j < 3; j++)
            C[3*i+j] = X[3*i+0]*Y[0+j] + X[3*i+1]*Y[3+j] + X[3*i+2]*Y[6+j];
        C[9+i] = X[3*i+0]*Y[9] + X[3*i+1]*Y[10] + X[3*i+2]*Y[11] + X[9+i];
    }
}

// One pointer-jump round (identity-parent for dead lanes; I∘val == val exact).
__device__ __forceinline__ bool jump_round(float val[12], int cb, int rnd,
                                           int base, int lane) {
    int sk = (cb >> (8 * (rnd + 1))) & 0xFF;
    bool live = (sk != 0xFF);
    if (!__any_sync(FULLM, live)) return false;
    int ps = live ? (base + sk) : lane;
    float p[12];
#pragma unroll
    for (int k = 0; k < 12; k++)
        p[k] = __shfl_sync(FULLM, val[k], ps, 32);
    p[0]  = live ? p[0]  : 1.0f;
    p[1]  = live ? p[1]  : 0.0f;
    p[2]  = live ? p[2]  : 0.0f;
    p[3]  = live ? p[3]  : 0.0f;
    p[4]  = live ? p[4]  : 1.0f;
    p[5]  = live ? p[5]  : 0.0f;
    p[6]  = live ? p[6]  : 0.0f;
    p[7]  = live ? p[7]  : 0.0f;
    p[8]  = live ? p[8]  : 1.0f;
    p[9]  = live ? p[9]  : 0.0f;
    p[10] = live ? p[10] : 0.0f;
    p[11] = live ? p[11] : 0.0f;
    float nw[12];
    combine_tf(p, val, nw);
#pragma unroll
    for (int k = 0; k < 12; k++)
        val[k] = nw[k];
    return true;
}

__global__ __launch_bounds__(192, 7) void struct_module_kernel(
    const float* __restrict__ out0,      // [N,17]
    const float* __restrict__ out1,      // [N,9]
    const float* __restrict__ pos,       // [N,3]
    const int*   __restrict__ ss,        // [N]
    const int*   __restrict__ rtype,     // [N]
    const int*   __restrict__ g_rdep,    // [22,24]
    float* __restrict__ outR,            // [N,72]
    float* __restrict__ outO,            // [N,12]
    int N)
{
    __shared__ int   s_chain[NRES * 8];
    __shared__ int   s_rdpk[NRES * 8];
    __shared__ float s_out[6][288];      // 6 warps x 288 floats R staging

    for (int idx = threadIdx.x; idx < NRES * 8; idx += blockDim.x) {
        s_chain[idx] = d_chain[idx];
        int rt = idx >> 3, li = idx & 7;
        int r0v = g_rdep[rt * 24 + li * 3 + 0];
        int r1v = g_rdep[rt * 24 + li * 3 + 1];
        int r2v = g_rdep[rt * 24 + li * 3 + 2];
        s_rdpk[idx] = r0v | (r1v << 8) | (r2v << 16);
    }
    __syncthreads();

    const int lane = threadIdx.x & 31;
    const int w    = threadIdx.x >> 5;
    const int li   = lane & 7;
    const int grp  = lane >> 3;
    const int base = lane & ~7;
    const int warpGlobal = (blockIdx.x * blockDim.x + threadIdx.x) >> 5;
    const int totalWarps = (gridDim.x * blockDim.x) >> 5;

    for (int r0 = warpGlobal * 4; r0 < N; r0 += totalWarps * 4) {
        int r = r0 + grp;
        bool valid = (r < N);
        int rc = valid ? r : (N - 1);

        int my_ss = ss[rc];
        int my_rt = rtype[rc];
        int e   = my_ss * NRES + my_rt;
        int cb  = s_chain[my_rt * 8 + li];
        int rp3 = s_rdpk[my_rt * 8 + li];

        // ---- T: 3 LDG.128, one 128B line per group each ----
        float T[12];
        {
            const float4* tp = reinterpret_cast<const float4*>(d_t2) + e * 24;
            float4 a = tp[li], b = tp[8 + li], c = tp[16 + li];
            T[0]=a.x; T[1]=a.y; T[2]=a.z;  T[3]=a.w;
            T[4]=b.x; T[5]=b.y; T[6]=b.z;  T[7]=b.w;
            T[8]=c.x; T[9]=c.y; T[10]=c.z; T[11]=c.w;
        }

        // ---- local transform combined with T -> o (leader-direct loads) ----
        float o[12];
        if (li == 0) {
            const float* p1 = out1 + (size_t)rc * 9;
            float v0x = __ldg(p1+0), v0y = __ldg(p1+1), v0z = __ldg(p1+2);
            float v1x = __ldg(p1+3), v1y = __ldg(p1+4), v1z = __ldg(p1+5);
            float t0  = __ldg(p1+6), t1  = __ldg(p1+7), t2  = __ldg(p1+8);
            const float* pp = pos + (size_t)rc * 3;
            float px = __ldg(pp+0), py = __ldg(pp+1), pz = __ldg(pp+2);

            float n2a = v0x*v0x + v0y*v0y + v0z*v0z;
            float i0 = rsqrtf(fmaxf(n2a, 1e-12f));
            float e0x = v0x*i0, e0y = v0y*i0, e0z = v0z*i0;
            float d = e0x*v1x + e0y*v1y + e0z*v1z;
            float u1x = v1x - e0x*d, u1y = v1y - e0y*d, u1z = v1z - e0z*d;
            float n2b = u1x*u1x + u1y*u1y + u1z*u1z;
            float i1 = rsqrtf(fmaxf(n2b, 1e-12f));
            float e1x = u1x*i1, e1y = u1y*i1, e1z = u1z*i1;
            float e2x = e0y*e1z - e0z*e1y;
            float e2y = e0z*e1x - e0x*e1z;
            float e2z = e0x*e1y - e0y*e1x;
            float B[12];
            B[0]=e0x; B[1]=e1x; B[2]=e2x;
            B[3]=e0y; B[4]=e1y; B[5]=e2y;
            B[6]=e0z; B[7]=e1z; B[8]=e2z;
            B[9]  = 0.1f * t0 + px;
            B[10] = 0.1f * t1 + py;
            B[11] = 0.1f * t2 + pz;
            combine_tf(T, B, o);
        } else {
            const float* q = out0 + (size_t)rc * 17 + 2*(li-1);
            float c0 = __ldg(q+0);
            float s0 = __ldg(q+1);
            float inv = rsqrtf(fmaxf(c0*c0 + s0*s0, 1e-12f));
            float c = c0 * inv, s = s0 * inv;
#pragma unroll
            for (int i = 0; i < 3; i++) {
                o[3*i+0] = T[3*i+0];
                o[3*i+1] = T[3*i+1]*c + T[3*i+2]*s;
                o[3*i+2] = T[3*i+2]*c - T[3*i+1]*s;
                o[9+i]   = T[9+i];
            }
        }

        // ---- immediate round ----
        float val[12];
        {
            int s0l = base + (cb & 0x7F);
            float pb[12];
#pragma unroll
            for (int k = 0; k < 12; k++)
                pb[k] = __shfl_sync(FULLM, o[k], s0l, 32);
            float nv[12];
            combine_tf(pb, o, nv);
            bool imm = (cb & 0x80) != 0;
#pragma unroll
            for (int k = 0; k < 12; k++)
                val[k] = imm ? nv[k] : o[k];
        }

        // ---- pointer-jump rounds with early exit ----
        if (jump_round(val, cb, 0, base, lane))
            if (jump_round(val, cb, 1, base, lane))
                jump_round(val, cb, 2, base, lane);

        // ---- atom gather: 3 atoms/lane via shfl, rigids from table ----
        {
            const float4* rpt = reinterpret_cast<const float4*>(d_r2) + e * 24;
#pragma unroll
            for (int asub = 0; asub < 3; asub++) {
                int a = li * 3 + asub;
                int gsrc = base + ((rp3 >> (8 * asub)) & 0xFF);
                float g[12];
#pragma unroll
                for (int k = 0; k < 12; k++)
                    g[k] = __shfl_sync(FULLM, val[k], gsrc, 32);
                float4 rv = rpt[asub * 8 + li];
                float* sp = &s_out[w][grp * 72 + a * 3];  // bank-conflict-free
                sp[0] = g[0]*rv.x + g[1]*rv.y + g[2]*rv.z + g[9];
                sp[1] = g[3]*rv.x + g[4]*rv.y + g[5]*rv.z + g[10];
                sp[2] = g[6]*rv.x + g[7]*rv.y + g[8]*rv.z + g[11];
            }
        }

        // ---- opr[:,0]: direct STG.128 from leader lanes ----
        if (li == 0 && valid) {
            float4* dO = reinterpret_cast<float4*>(outO + (size_t)r * 12);
            dO[0] = make_float4(val[0], val[1], val[2],  val[3]);
            dO[1] = make_float4(val[4], val[5], val[6],  val[7]);
            dO[2] = make_float4(val[8], val[9], val[10], val[11]);
        }
        __syncwarp();

        // ---- coalesced R flush ----
        int rem = N - r0;
        int nR4 = ((rem >= 4) ? 4 : rem) * 18;
        const float4* s4 = reinterpret_cast<const float4*>(&s_out[w][0]);
        float4* dR = reinterpret_cast<float4*>(outR + (size_t)r0 * 72);
#pragma unroll
        for (int i = 0; i < 3; i++) {
            int idx = lane + i * 32;
            if (idx < nR4)
                dR[idx] = s4[idx];
        }
        __syncwarp();
    }
}

extern "C" void kernel_launch(void* const* d_in, const int* in_sizes, int n_in,
                              void* d_out, int out_size) {
    const float* out0 = (const float*)d_in[0];
    const float* out1 = (const float*)d_in[1];
    const float* posp = (const float*)d_in[2];
    const int*   ssp  = (const int*)d_in[3];
    const int*   rtp  = (const int*)d_in[4];
    const float* gt   = (const float*)d_in[5];
    const float* gr   = (const float*)d_in[6];
    const int*   td   = (const int*)d_in[7];
    const int*   rd   = (const int*)d_in[8];
    int N = in_sizes[3];
    float* R = (float*)d_out;
    float* O = R + (size_t)N * 72;

    reformat_kernel<<<NE + 1, 192>>>(gt, gr, td);
    // 7 blocks/SM x 148 SMs
    struct_module_kernel<<<1036, 192>>>(out0, out1, posp, ssp, rtp,
                                        rd, R, O, N);
}

// round 15
// speedup vs baseline: 1.0680x; 1.0680x over previous
#include <cuda_runtime.h>

// Model_21569325760600: structure-module forward.
// R7 body byte-identical; ONLY the launch shape changes: 128 thr x 8 blocks/SM
// (same 64-reg budget as 192x5, +2 resident warps/SM). Dual-stream, static
// pointer-jump chain tables, identity-parent rounds, staged R flush.

#define NRES  22
#define NE    66
#define FULLM 0xffffffffu

__device__ __align__(16) float d_t2[NE * 96];
__device__ __align__(16) float d_r2[NE * 96];
__device__ int d_chain[NRES * 8];

__global__ void reformat_kernel(const float* __restrict__ g_trans,   // [66,8,12]
                                const float* __restrict__ g_rigid,   // [66,24,3]
                                const int*   __restrict__ g_tdep) {  // [22,8]
    __shared__ int sp[NRES][8];
    int t = threadIdx.x;
    if (blockIdx.x < NE) {
        if (t < 96) {
            int e = blockIdx.x;
            int j4 = t >> 5;
            int li = (t >> 2) & 7;
            int k  = t & 3;
            d_t2[e * 96 + t] = g_trans[e * 96 + li * 12 + j4 * 4 + k];
            d_r2[e * 96 + t] = (k < 3) ? g_rigid[e * 72 + (li * 3 + j4) * 3 + k] : 0.0f;
        }
        return;
    }
    if (t < NRES * 8) {
        int rt = t >> 3, li = t & 7;
        int dd = g_tdep[rt * 8 + li];
        int imm = (li != 0 && dd >= li) ? 1 : 0;
        int p0 = (li != 0 && dd < li) ? dd : -1;
        sp[rt][li] = p0;
        __syncthreads();
        int p1 = (p0 >= 0) ? sp[rt][p0] : -1;
        __syncthreads();
        sp[rt][li] = p1;
        __syncthreads();
        int p2 = (p1 >= 0) ? sp[rt][p1] : -1;
        d_chain[t] = (dd & 0x7F) | (imm << 7) |
                     ((p0 & 0xFF) << 8) | ((p1 & 0xFF) << 16) | ((p2 & 0xFF) << 24);
    }
}

__device__ __forceinline__ void combine_tf(const float* __restrict__ X,
                                           const float* __restrict__ Y,
                                           float* __restrict__ C) {
#pragma unroll
    for (int i = 0; i < 3; i++) {
#pragma unroll
        for (int j = 0; j < 3; j++)
            C[3*i+j] = X[3*i+0]*Y[0+j] + X[3*i+1]*Y[3+j] + X[3*i+2]*Y[6+j];
        C[9+i] = X[3*i+0]*Y[9] + X[3*i+1]*Y[10] + X[3*i+2]*Y[11] + X[9+i];
    }
}

// One pointer-jump round for one stream. Identity-parent for dead lanes makes
// the combine unconditional (I∘val == val exactly). Returns false if whole
// warp dead for this stream (round skipped).
__device__ __forceinline__ bool jump_round(float val[12], int cb, int rnd,
                                           int base, int lane) {
    int sk = (cb >> (8 * (rnd + 1))) & 0xFF;
    bool live = (sk != 0xFF);
    if (!__any_sync(FULLM, live)) return false;
    int ps = live ? (base + sk) : lane;
    float p[12];
#pragma unroll
    for (int k = 0; k < 12; k++)
        p[k] = __shfl_sync(FULLM, val[k], ps, 32);
    p[0]  = live ? p[0]  : 1.0f;
    p[1]  = live ? p[1]  : 0.0f;
    p[2]  = live ? p[2]  : 0.0f;
    p[3]  = live ? p[3]  : 0.0f;
    p[4]  = live ? p[4]  : 1.0f;
    p[5]  = live ? p[5]  : 0.0f;
    p[6]  = live ? p[6]  : 0.0f;
    p[7]  = live ? p[7]  : 0.0f;
    p[8]  = live ? p[8]  : 1.0f;
    p[9]  = live ? p[9]  : 0.0f;
    p[10] = live ? p[10] : 0.0f;
    p[11] = live ? p[11] : 0.0f;
    float nw[12];
    combine_tf(p, val, nw);
#pragma unroll
    for (int k = 0; k < 12; k++)
        val[k] = nw[k];
    return true;
}

// Front for one 4-residue stream: post-base transform o[12] + table index e,
// chain word cb, packed rdep rp3. Leader lanes load bb inputs directly.
__device__ __forceinline__ void stream_front(
    const float* __restrict__ out0, const float* __restrict__ out1,
    const float* __restrict__ pos,
    const int* __restrict__ ss, const int* __restrict__ rtype,
    const int* __restrict__ s_chain, const int* __restrict__ s_rdpk,
    int r0s, int N, int li, int grp,
    float o[12], int& e, int& cb, int& rp3)
{
    int r = r0s + grp;
    bool valid = (r >= 0) && (r < N);
    int rc = valid ? r : (N - 1);

    int my_ss = ss[rc];
    int my_rt = rtype[rc];
    e   = my_ss * NRES + my_rt;
    cb  = s_chain[my_rt * 8 + li];
    rp3 = s_rdpk[my_rt * 8 + li];

    // T: 3 LDG.128, one 128B line per group each
    float T[12];
    {
        const float4* tp = reinterpret_cast<const float4*>(d_t2) + e * 24;
        float4 a = tp[li], b = tp[8 + li], c = tp[16 + li];
        T[0]=a.x; T[1]=a.y; T[2]=a.z;  T[3]=a.w;
        T[4]=b.x; T[5]=b.y; T[6]=b.z;  T[7]=b.w;
        T[8]=c.x; T[9]=c.y; T[10]=c.z; T[11]=c.w;
    }

    if (li == 0) {
        const float* p1 = out1 + (size_t)rc * 9;
        float v0x = __ldg(p1+0), v0y = __ldg(p1+1), v0z = __ldg(p1+2);
        float v1x = __ldg(p1+3), v1y = __ldg(p1+4), v1z = __ldg(p1+5);
        float t0  = __ldg(p1+6), t1  = __ldg(p1+7), t2  = __ldg(p1+8);
        const float* pp = pos + (size_t)rc * 3;
        float px = __ldg(pp+0), py = __ldg(pp+1), pz = __ldg(pp+2);

        float n2a = v0x*v0x + v0y*v0y + v0z*v0z;
        float i0 = rsqrtf(fmaxf(n2a, 1e-12f));
        float e0x = v0x*i0, e0y = v0y*i0, e0z = v0z*i0;
        float d = e0x*v1x + e0y*v1y + e0z*v1z;
        float u1x = v1x - e0x*d, u1y = v1y - e0y*d, u1z = v1z - e0z*d;
        float n2b = u1x*u1x + u1y*u1y + u1z*u1z;
        float i1 = rsqrtf(fmaxf(n2b, 1e-12f));
        float e1x = u1x*i1, e1y = u1y*i1, e1z = u1z*i1;
        float e2x = e0y*e1z - e0z*e1y;
        float e2y = e0z*e1x - e0x*e1z;
        float e2z = e0x*e1y - e0y*e1x;
        float B[12];
        B[0]=e0x; B[1]=e1x; B[2]=e2x;
        B[3]=e0y; B[4]=e1y; B[5]=e2y;
        B[6]=e0z; B[7]=e1z; B[8]=e2z;
        B[9]  = 0.1f * t0 + px;
        B[10] = 0.1f * t1 + py;
        B[11] = 0.1f * t2 + pz;
        combine_tf(T, B, o);
    } else {
        const float* q = out0 + (size_t)rc * 17 + 2*(li-1);
        float c0 = __ldg(q+0);
        float s0 = __ldg(q+1);
        float inv = rsqrtf(fmaxf(c0*c0 + s0*s0, 1e-12f));
        float c = c0 * inv, s = s0 * inv;
#pragma unroll
        for (int i = 0; i < 3; i++) {
            o[3*i+0] = T[3*i+0];
            o[3*i+1] = T[3*i+1]*c + T[3*i+2]*s;
            o[3*i+2] = T[3*i+2]*c - T[3*i+1]*s;
            o[9+i]   = T[9+i];
        }
    }
}

__global__ __launch_bounds__(128, 8) void struct_module_kernel(
    const float* __restrict__ out0,      // [N,17]
    const float* __restrict__ out1,      // [N,9]
    const float* __restrict__ pos,       // [N,3]
    const int*   __restrict__ ss,        // [N]
    const int*   __restrict__ rtype,     // [N]
    const int*   __restrict__ g_rdep,    // [22,24]
    float* __restrict__ outR,            // [N,72]
    float* __restrict__ outO,            // [N,12]
    int N)
{
    __shared__ int   s_chain[NRES * 8];
    __shared__ int   s_rdpk[NRES * 8];
    __shared__ float s_out[4][576];      // 4 warps x 2 streams x 288

    for (int idx = threadIdx.x; idx < NRES * 8; idx += blockDim.x) {
        s_chain[idx] = d_chain[idx];
        int rt = idx >> 3, li = idx & 7;
        int r0v = g_rdep[rt * 24 + li * 3 + 0];
        int r1v = g_rdep[rt * 24 + li * 3 + 1];
        int r2v = g_rdep[rt * 24 + li * 3 + 2];
        s_rdpk[idx] = r0v | (r1v << 8) | (r2v << 16);
    }
    __syncthreads();

    const int lane = threadIdx.x & 31;
    const int w    = threadIdx.x >> 5;
    const int li   = lane & 7;
    const int grp  = lane >> 3;
    const int base = lane & ~7;
    const int warpGlobal = (blockIdx.x * blockDim.x + threadIdx.x) >> 5;
    const int totalWarps = (gridDim.x * blockDim.x) >> 5;

    for (int r0 = warpGlobal * 8; r0 < N; r0 += totalWarps * 8) {
        float vA[12], vB[12];
        int eA, cbA, rpA, eB, cbB, rpB;
        {
            float oA[12], oB[12];
            stream_front(out0, out1, pos, ss, rtype, s_chain, s_rdpk,
                         r0,     N, li, grp, oA, eA, cbA, rpA);
            stream_front(out0, out1, pos, ss, rtype, s_chain, s_rdpk,
                         r0 + 4, N, li, grp, oB, eB, cbB, rpB);

            // immediate round, dual-interleaved
            int sA = base + (cbA & 0x7F);
            int sB = base + (cbB & 0x7F);
            float pA[12], pB[12];
#pragma unroll
            for (int k = 0; k < 12; k++) {
                pA[k] = __shfl_sync(FULLM, oA[k], sA, 32);
                pB[k] = __shfl_sync(FULLM, oB[k], sB, 32);
            }
            float nA[12], nB[12];
            combine_tf(pA, oA, nA);
            combine_tf(pB, oB, nB);
            bool immA = (cbA & 0x80) != 0;
            bool immB = (cbB & 0x80) != 0;
#pragma unroll
            for (int k = 0; k < 12; k++) {
                vA[k] = immA ? nA[k] : oA[k];
                vB[k] = immB ? nB[k] : oB[k];
            }
        }

        // round 1 (usually live for both): per-stream bodies back-to-back
        bool goA = jump_round(vA, cbA, 0, base, lane);
        bool goB = jump_round(vB, cbB, 0, base, lane);
        // rounds 2-3: per-stream skip
        if (goA) { if (jump_round(vA, cbA, 1, base, lane)) jump_round(vA, cbA, 2, base, lane); }
        if (goB) { if (jump_round(vB, cbB, 1, base, lane)) jump_round(vB, cbB, 2, base, lane); }

        // ---- atom gathers, per stream (register-pressure friendly) ----
        {
            const float4* rpt = reinterpret_cast<const float4*>(d_r2) + eA * 24;
#pragma unroll
            for (int asub = 0; asub < 3; asub++) {
                int a = li * 3 + asub;
                int gsrc = base + ((rpA >> (8 * asub)) & 0xFF);
                float g[12];
#pragma unroll
                for (int k = 0; k < 12; k++)
                    g[k] = __shfl_sync(FULLM, vA[k], gsrc, 32);
                float4 rv = rpt[asub * 8 + li];
                float* sp = &s_out[w][grp * 72 + a * 3];
                sp[0] = g[0]*rv.x + g[1]*rv.y + g[2]*rv.z + g[9];
                sp[1] = g[3]*rv.x + g[4]*rv.y + g[5]*rv.z + g[10];
                sp[2] = g[6]*rv.x + g[7]*rv.y + g[8]*rv.z + g[11];
            }
        }
        {
            const float4* rpt = reinterpret_cast<const float4*>(d_r2) + eB * 24;
#pragma unroll
            for (int asub = 0; asub < 3; asub++) {
                int a = li * 3 + asub;
                int gsrc = base + ((rpB >> (8 * asub)) & 0xFF);
                float g[12];
#pragma unroll
                for (int k = 0; k < 12; k++)
                    g[k] = __shfl_sync(FULLM, vB[k], gsrc, 32);
                float4 rv = rpt[asub * 8 + li];
                float* sp = &s_out[w][288 + grp * 72 + a * 3];
                sp[0] = g[0]*rv.x + g[1]*rv.y + g[2]*rv.z + g[9];
                sp[1] = g[3]*rv.x + g[4]*rv.y + g[5]*rv.z + g[10];
                sp[2] = g[6]*rv.x + g[7]*rv.y + g[8]*rv.z + g[11];
            }
        }

        // ---- opr[:,0]: direct STG.128 from leader lanes ----
        if (li == 0) {
            int rA = r0 + grp;
            if (rA < N) {
                float4* dO = reinterpret_cast<float4*>(outO + (size_t)rA * 12);
                dO[0] = make_float4(vA[0], vA[1], vA[2],  vA[3]);
                dO[1] = make_float4(vA[4], vA[5], vA[6],  vA[7]);
                dO[2] = make_float4(vA[8], vA[9], vA[10], vA[11]);
            }
            int rB = r0 + 4 + grp;
            if (rB < N) {
                float4* dO = reinterpret_cast<float4*>(outO + (size_t)rB * 12);
                dO[0] = make_float4(vB[0], vB[1], vB[2],  vB[3]);
                dO[1] = make_float4(vB[4], vB[5], vB[6],  vB[7]);
                dO[2] = make_float4(vB[8], vB[9], vB[10], vB[11]);
            }
        }
        __syncwarp();

        // ---- coalesced R flush ----
        int remA = N - r0;
        int nA4 = ((remA >= 4) ? 4 : remA) * 18;
        int remB = N - (r0 + 4);
        int nB4 = ((remB >= 4) ? 4 : (remB > 0 ? remB : 0)) * 18;
        const float4* s4a = reinterpret_cast<const float4*>(&s_out[w][0]);
        const float4* s4b = reinterpret_cast<const float4*>(&s_out[w][288]);
        float4* dRa = reinterpret_cast<float4*>(outR + (size_t)r0 * 72);
        float4* dRb = reinterpret_cast<float4*>(outR + (size_t)(r0 + 4) * 72);
#pragma unroll
        for (int i = 0; i < 3; i++) {
            int idx = lane + i * 32;
            if (idx < nA4) dRa[idx] = s4a[idx];
            if (idx < nB4) dRb[idx] = s4b[idx];
        }
        __syncwarp();
    }
}

extern "C" void kernel_launch(void* const* d_in, const int* in_sizes, int n_in,
                              void* d_out, int out_size) {
    const float* out0 = (const float*)d_in[0];
    const float* out1 = (const float*)d_in[1];
    const float* posp = (const float*)d_in[2];
    const int*   ssp  = (const int*)d_in[3];
    const int*   rtp  = (const int*)d_in[4];
    const float* gt   = (const float*)d_in[5];
    const float* gr   = (const float*)d_in[6];
    const int*   td   = (const int*)d_in[7];
    const int*   rd   = (const int*)d_in[8];
    int N = in_sizes[3];
    float* R = (float*)d_out;
    float* O = R + (size_t)N * 72;

    reformat_kernel<<<NE + 1, 192>>>(gt, gr, td);
    // 8 blocks/SM x 148 SMs
    struct_module_kernel<<<1184, 128>>>(out0, out1, posp, ssp, rtp,
                                        rd, R, O, N);
}